// round 13
// baseline (speedup 1.0000x reference)
#include <cuda_runtime.h>
#include <math_constants.h>

#define BB 64
#define LL 4096
#define DD 512
#define NS 8                 // L-splits per batch row -> 512 worker blocks
#define CHUNK (LL / NS)      // 512 rows per CTA (compile-time)
#define WARPS 8
#define NTHREADS (WARPS * 32)
#define NWORK (BB * NS)      // 512
#define NGRID (NWORK + BB)   // 64 combiner blocks (first) + 512 workers = 576
#define SSTR (DD + 4)        // scratch row stride: 516 floats, 16B-aligned

// scratch: per (b, split): c[512] at local-max reference
__device__ __align__(16) float  g_scratch[BB * NS * SSTR];
__device__ __align__(16) float2 g_ms[BB * NS];   // packed (m, s) sidecar
__device__ int g_flag[BB * NS]; // zero-init; combiner resets -> replay-safe

static __device__ __forceinline__ float4 ldcg4(const float4* p) {
    float4 v;
    asm volatile("ld.global.cg.v4.f32 {%0,%1,%2,%3}, [%4];"
                 : "=f"(v.x), "=f"(v.y), "=f"(v.z), "=f"(v.w) : "l"(p));
    return v;
}
static __device__ __forceinline__ float2 ldcg2(const float2* p) {
    float2 v;
    asm volatile("ld.global.cg.v2.f32 {%0,%1}, [%2];"
                 : "=f"(v.x), "=f"(v.y) : "l"(p));
    return v;
}
static __device__ __forceinline__ int ld_acq(const int* p) {
    int v;
    asm volatile("ld.global.acquire.gpu.b32 %0, [%1];" : "=r"(v) : "l"(p));
    return v;
}
static __device__ __forceinline__ void st_rel(int* p, int v) {
    asm volatile("st.global.release.gpu.b32 [%0], %1;" :: "l"(p), "r"(v)
                 : "memory");
}

__global__ void __launch_bounds__(NTHREADS, 4)
attn_one(const float* __restrict__ h, const float* __restrict__ E,
         float* __restrict__ outp) {
    const int tid  = threadIdx.x;
    const int wid  = tid >> 5;
    const int lane = tid & 31;

    // ===== combiner blocks (0..BB-1): online merge in slot order ============
    if (blockIdx.x < BB) {
        const int b = blockIdx.x;
        const float* base = g_scratch + (size_t)b * NS * SSTR;

        float4 acc   = make_float4(0.f, 0.f, 0.f, 0.f);
        float  m_run = -CUDART_INF_F;
        float  s_run = 0.f;

#pragma unroll
        for (int i = 0; i < NS; i++) {
            if (tid == 0) {
                while (ld_acq(&g_flag[b * NS + i]) == 0) __nanosleep(32);
            }
            __syncthreads();

            if (tid < DD / 4) {
                const float2 ms = ldcg2(&g_ms[b * NS + i]);   // broadcast line
                float sc_new;
                if (ms.x > m_run) {          // rescale accumulator to new max
                    const float r = __expf(m_run - ms.x);
                    acc.x *= r; acc.y *= r; acc.z *= r; acc.w *= r;
                    s_run *= r;
                    m_run = ms.x;
                    sc_new = 1.f;
                } else {
                    sc_new = __expf(ms.x - m_run);
                }
                const float4 v =
                    ldcg4((const float4*)(base + (size_t)i * SSTR) + tid);
                acc.x = fmaf(v.x, sc_new, acc.x);
                acc.y = fmaf(v.y, sc_new, acc.y);
                acc.z = fmaf(v.z, sc_new, acc.z);
                acc.w = fmaf(v.w, sc_new, acc.w);
                s_run = fmaf(ms.y, sc_new, s_run);
            }
        }

        if (tid < DD / 4) {
            const float inv = 1.f / (s_run * (float)LL);
            acc.x *= inv; acc.y *= inv; acc.z *= inv; acc.w *= inv;
            ((float4*)(outp + (size_t)b * DD))[tid] = acc;
        }
        __syncthreads();
        if (tid < NS) g_flag[b * NS + tid] = 0;   // reset for next replay
        return;
    }

    // ================= worker blocks (mainloop unchanged) ===================
    const int wk    = blockIdx.x - BB;
    const int b     = wk / NS;
    const int split = wk % NS;

    const float4* h4  = (const float4*)(h + (size_t)b * DD);
    const float4* Eb  = (const float4*)(E + (size_t)b * LL * DD);
    const int row0    = split * CHUNK;

    float m = -CUDART_INF_F;
    float s = 0.f;
    float4 c[4];
#pragma unroll
    for (int q = 0; q < 4; q++) c[q] = make_float4(0.f, 0.f, 0.f, 0.f);

    // one row per warp-iteration; h streamed from L1 (stays resident there)
    for (int r = wid; r < CHUNK; r += WARPS) {
        const float4* row = Eb + (size_t)(row0 + r) * (DD / 4);
        float4 v[4];
#pragma unroll
        for (int q = 0; q < 4; q++) v[q] = __ldcs(row + lane + 32 * q);

        float d0 = 0.f, d1 = 0.f;              // two chains halve FMA latency
#pragma unroll
        for (int q = 0; q < 4; q++) {
            const float4 hq = __ldg(h4 + lane + 32 * q);   // L1 hit
            d0 = fmaf(v[q].x, hq.x, d0);
            d1 = fmaf(v[q].y, hq.y, d1);
            d0 = fmaf(v[q].z, hq.z, d0);
            d1 = fmaf(v[q].w, hq.w, d1);
        }
        float e = d0 + d1;
#pragma unroll
        for (int o = 16; o > 0; o >>= 1)
            e += __shfl_xor_sync(0xffffffffu, e, o);

        if (e > m) {                           // warp-uniform, rarely taken
            const float sc = __expf(m - e);
            s *= sc;
#pragma unroll
            for (int q = 0; q < 4; q++) {
                c[q].x *= sc; c[q].y *= sc; c[q].z *= sc; c[q].w *= sc;
            }
            m = e;
        }
        const float p = __expf(e - m);
        s += p;
#pragma unroll
        for (int q = 0; q < 4; q++) {
            c[q].x = fmaf(p, v[q].x, c[q].x);
            c[q].y = fmaf(p, v[q].y, c[q].y);
            c[q].z = fmaf(p, v[q].z, c[q].z);
            c[q].w = fmaf(p, v[q].w, c[q].w);
        }
    }

    // ---- combine the 8 warps within the CTA ----
    __shared__ __align__(16) float sm_c[WARPS][DD];
    __shared__ float sm_m[WARPS], sm_s[WARPS], sm_sc[WARPS];
    __shared__ float sm_mg, sm_stot;

#pragma unroll
    for (int q = 0; q < 4; q++) {
        const int d0i = 4 * lane + 128 * q;
        sm_c[wid][d0i + 0] = c[q].x;
        sm_c[wid][d0i + 1] = c[q].y;
        sm_c[wid][d0i + 2] = c[q].z;
        sm_c[wid][d0i + 3] = c[q].w;
    }
    if (lane == 0) { sm_m[wid] = m; sm_s[wid] = s; }
    __syncthreads();

    if (wid == 0) {
        float mw = (lane < WARPS) ? sm_m[lane] : -CUDART_INF_F;
        float mg = mw;
#pragma unroll
        for (int o = 16; o > 0; o >>= 1)
            mg = fmaxf(mg, __shfl_xor_sync(0xffffffffu, mg, o));
        float sc = (lane < WARPS) ? __expf(mw - mg) : 0.f;
        float st = (lane < WARPS) ? sm_s[lane] * sc : 0.f;
#pragma unroll
        for (int o = 16; o > 0; o >>= 1)
            st += __shfl_xor_sync(0xffffffffu, st, o);
        if (lane < WARPS) sm_sc[lane] = sc;
        if (lane == 0) { sm_mg = mg; sm_stot = st; }
    }
    __syncthreads();

    // vectorized flush: 128 threads x float4
    float* out = g_scratch + ((size_t)b * NS + split) * SSTR;
    if (tid < DD / 4) {
        float4 acc = make_float4(0.f, 0.f, 0.f, 0.f);
#pragma unroll
        for (int w = 0; w < WARPS; w++) {
            const float4 v = ((const float4*)sm_c[w])[tid];
            const float sc = sm_sc[w];
            acc.x = fmaf(v.x, sc, acc.x);
            acc.y = fmaf(v.y, sc, acc.y);
            acc.z = fmaf(v.z, sc, acc.z);
            acc.w = fmaf(v.w, sc, acc.w);
        }
        ((float4*)out)[tid] = acc;
    }
    if (tid == 0) g_ms[b * NS + split] = make_float2(sm_mg, sm_stot);

    // publish: per-slot release flag (orders prior writes)
    __syncthreads();
    if (tid == 0) st_rel(&g_flag[b * NS + split], 1);
}

extern "C" void kernel_launch(void* const* d_in, const int* in_sizes, int n_in,
                              void* d_out, int out_size) {
    const float* h = (const float*)d_in[0];   // current_hidden [64, 512]
    const float* E = (const float*)d_in[1];   // encoder_outputs [64, 4096, 512]
    float* outp = (float*)d_out;              // [64, 512]

    attn_one<<<NGRID, NTHREADS>>>(h, E, outp);
}

// round 14
// speedup vs baseline: 1.0242x; 1.0242x over previous
#include <cuda_runtime.h>
#include <math_constants.h>

#define BB 64
#define LL 4096
#define DD 512
#define NS 8                 // L-splits per batch row -> 512 worker blocks
#define CHUNK (LL / NS)      // 512 rows per CTA (compile-time)
#define WARPS 8
#define NTHREADS (WARPS * 32)
#define NWORK (BB * NS)      // 512
#define NGRID (NWORK + BB)   // 64 combiner blocks (first) + 512 workers = 576
#define SSTR (DD + 4)        // scratch row stride: 516 floats, 16B-aligned

// scratch: per (b, split): c[512] at local-max reference
__device__ __align__(16) float  g_scratch[BB * NS * SSTR];
__device__ __align__(16) float2 g_ms[BB * NS];   // packed (m, s) sidecar
__device__ int g_done[BB];   // zero-init; combiner resets -> graph-replay safe

static __device__ __forceinline__ float4 ldcg4(const float4* p) {
    float4 v;
    asm volatile("ld.global.cg.v4.f32 {%0,%1,%2,%3}, [%4];"
                 : "=f"(v.x), "=f"(v.y), "=f"(v.z), "=f"(v.w) : "l"(p));
    return v;
}
static __device__ __forceinline__ float2 ldcg2(const float2* p) {
    float2 v;
    asm volatile("ld.global.cg.v2.f32 {%0,%1}, [%2];"
                 : "=f"(v.x), "=f"(v.y) : "l"(p));
    return v;
}
static __device__ __forceinline__ int ld_acq(const int* p) {
    int v;
    asm volatile("ld.global.acquire.gpu.b32 %0, [%1];" : "=r"(v) : "l"(p));
    return v;
}
static __device__ __forceinline__ void red_release_add(int* p, int v) {
    asm volatile("red.release.gpu.global.add.s32 [%0], %1;" :: "l"(p), "r"(v)
                 : "memory");
}

__global__ void __launch_bounds__(NTHREADS, 4)
attn_one(const float* __restrict__ h, const float* __restrict__ E,
         float* __restrict__ outp) {
    const int tid  = threadIdx.x;
    const int wid  = tid >> 5;
    const int lane = tid & 31;

    // ================= combiner blocks (0..BB-1): resident from wave 1 ======
    if (blockIdx.x < BB) {
        const int b = blockIdx.x;

        __shared__ float sm2_sc[NS];
        __shared__ float sm2_stot;

        if (tid == 0) {
            // long sleep: minimal spin traffic during the streaming phase
            while (ld_acq(&g_done[b]) != NS) __nanosleep(256);
        }
        __syncthreads();

        const float* base = g_scratch + (size_t)b * NS * SSTR;

        if (tid < 32) {      // packed (m,s): NS consecutive float2 = 1 line
            float2 ms = (tid < NS) ? ldcg2(&g_ms[b * NS + tid])
                                   : make_float2(-CUDART_INF_F, 0.f);
            float mg = ms.x;
#pragma unroll
            for (int o = 16; o > 0; o >>= 1)
                mg = fmaxf(mg, __shfl_xor_sync(0xffffffffu, mg, o));
            float sc = (tid < NS) ? __expf(ms.x - mg) : 0.f;
            float st = ms.y * sc;
#pragma unroll
            for (int o = 16; o > 0; o >>= 1)
                st += __shfl_xor_sync(0xffffffffu, st, o);
            if (tid < NS) sm2_sc[tid] = sc;
            if (tid == 0) sm2_stot = st;
        }
        __syncthreads();

        if (tid < DD / 4) {                    // 128 threads, float4 lanes
            const float inv = 1.f / (sm2_stot * (float)LL);
            float4 acc = make_float4(0.f, 0.f, 0.f, 0.f);
#pragma unroll
            for (int i = 0; i < NS; i++) {
                const float4 v =
                    ldcg4((const float4*)(base + (size_t)i * SSTR) + tid);
                const float sc = sm2_sc[i];
                acc.x = fmaf(v.x, sc, acc.x);
                acc.y = fmaf(v.y, sc, acc.y);
                acc.z = fmaf(v.z, sc, acc.z);
                acc.w = fmaf(v.w, sc, acc.w);
            }
            acc.x *= inv; acc.y *= inv; acc.z *= inv; acc.w *= inv;
            ((float4*)(outp + (size_t)b * DD))[tid] = acc;
        }
        if (tid == 0) g_done[b] = 0;      // reset for next graph replay
        return;
    }

    // ================= worker blocks (mainloop; E via evict-first .cs) ======
    const int wk    = blockIdx.x - BB;
    const int b     = wk / NS;
    const int split = wk % NS;

    const float4* h4  = (const float4*)(h + (size_t)b * DD);
    const float4* Eb  = (const float4*)(E + (size_t)b * LL * DD);
    const int row0    = split * CHUNK;

    float m = -CUDART_INF_F;
    float s = 0.f;
    float4 c[4];
#pragma unroll
    for (int q = 0; q < 4; q++) c[q] = make_float4(0.f, 0.f, 0.f, 0.f);

    // one row per warp-iteration; h streamed from L1 (stays resident there)
    for (int r = wid; r < CHUNK; r += WARPS) {
        const float4* row = Eb + (size_t)(row0 + r) * (DD / 4);
        float4 v[4];
#pragma unroll
        for (int q = 0; q < 4; q++) v[q] = __ldcs(row + lane + 32 * q);

        float d0 = 0.f, d1 = 0.f;              // two chains halve FMA latency
#pragma unroll
        for (int q = 0; q < 4; q++) {
            const float4 hq = __ldg(h4 + lane + 32 * q);   // L1 hit
            d0 = fmaf(v[q].x, hq.x, d0);
            d1 = fmaf(v[q].y, hq.y, d1);
            d0 = fmaf(v[q].z, hq.z, d0);
            d1 = fmaf(v[q].w, hq.w, d1);
        }
        float e = d0 + d1;
#pragma unroll
        for (int o = 16; o > 0; o >>= 1)
            e += __shfl_xor_sync(0xffffffffu, e, o);

        if (e > m) {                           // warp-uniform, rarely taken
            const float sc = __expf(m - e);
            s *= sc;
#pragma unroll
            for (int q = 0; q < 4; q++) {
                c[q].x *= sc; c[q].y *= sc; c[q].z *= sc; c[q].w *= sc;
            }
            m = e;
        }
        const float p = __expf(e - m);
        s += p;
#pragma unroll
        for (int q = 0; q < 4; q++) {
            c[q].x = fmaf(p, v[q].x, c[q].x);
            c[q].y = fmaf(p, v[q].y, c[q].y);
            c[q].z = fmaf(p, v[q].z, c[q].z);
            c[q].w = fmaf(p, v[q].w, c[q].w);
        }
    }

    // ---- combine the 8 warps within the CTA ----
    __shared__ __align__(16) float sm_c[WARPS][DD];
    __shared__ float sm_m[WARPS], sm_s[WARPS], sm_sc[WARPS];
    __shared__ float sm_mg, sm_stot;

#pragma unroll
    for (int q = 0; q < 4; q++) {
        const int d0i = 4 * lane + 128 * q;
        sm_c[wid][d0i + 0] = c[q].x;
        sm_c[wid][d0i + 1] = c[q].y;
        sm_c[wid][d0i + 2] = c[q].z;
        sm_c[wid][d0i + 3] = c[q].w;
    }
    if (lane == 0) { sm_m[wid] = m; sm_s[wid] = s; }
    __syncthreads();

    if (wid == 0) {
        float mw = (lane < WARPS) ? sm_m[lane] : -CUDART_INF_F;
        float mg = mw;
#pragma unroll
        for (int o = 16; o > 0; o >>= 1)
            mg = fmaxf(mg, __shfl_xor_sync(0xffffffffu, mg, o));
        float sc = (lane < WARPS) ? __expf(mw - mg) : 0.f;
        float st = (lane < WARPS) ? sm_s[lane] * sc : 0.f;
#pragma unroll
        for (int o = 16; o > 0; o >>= 1)
            st += __shfl_xor_sync(0xffffffffu, st, o);
        if (lane < WARPS) sm_sc[lane] = sc;
        if (lane == 0) { sm_mg = mg; sm_stot = st; }
    }
    __syncthreads();

    // vectorized flush: 128 threads x float4
    float* out = g_scratch + ((size_t)b * NS + split) * SSTR;
    if (tid < DD / 4) {
        float4 acc = make_float4(0.f, 0.f, 0.f, 0.f);
#pragma unroll
        for (int w = 0; w < WARPS; w++) {
            const float4 v = ((const float4*)sm_c[w])[tid];
            const float sc = sm_sc[w];
            acc.x = fmaf(v.x, sc, acc.x);
            acc.y = fmaf(v.y, sc, acc.y);
            acc.z = fmaf(v.z, sc, acc.z);
            acc.w = fmaf(v.w, sc, acc.w);
        }
        ((float4*)out)[tid] = acc;
    }
    if (tid == 0) g_ms[b * NS + split] = make_float2(sm_mg, sm_stot);

    // publish: release-ordered increment (orders prior writes, no full membar)
    __syncthreads();
    if (tid == 0) red_release_add(&g_done[b], 1);
}

extern "C" void kernel_launch(void* const* d_in, const int* in_sizes, int n_in,
                              void* d_out, int out_size) {
    const float* h = (const float*)d_in[0];   // current_hidden [64, 512]
    const float* E = (const float*)d_in[1];   // encoder_outputs [64, 4096, 512]
    float* outp = (float*)d_out;              // [64, 512]

    attn_one<<<NGRID, NTHREADS>>>(h, E, outp);
}